// round 12
// baseline (speedup 1.0000x reference)
#include <cuda_runtime.h>
#include <cstdint>

#define BATCH 8
#define CIN   64
#define COUT  64
#define Hdim  64
#define Wdim  64
#define CTOT  69
#define HW    (Hdim*Wdim)
#define NPIX  (BATCH*HW)

// Scratch (static device globals — no allocation)
__device__ float g_conv[BATCH*COUT*HW];   // raw conv output (pre-BN)
__device__ float g_sq[NPIX];              // 1x1-conv "shape query"
__device__ float g_mu[COUT];
__device__ float g_rs[COUT];
__device__ __align__(16) float g_wt[9*4096];  // weights in B-fragment order

__device__ __forceinline__ int clampi(int v, int lo, int hi) {
    return v < lo ? lo : (v > hi ? hi : v);
}
__device__ __forceinline__ float f2tf32f(float f) {
    uint32_t r; asm("cvt.rna.tf32.f32 %0, %1;" : "=r"(r) : "f"(f));
    return __uint_as_float(r);
}

// m16n8k8 tf32 mma: D += A*B (D==C, fp32 accum). a: 4 regs, b: 2 regs.
__device__ __forceinline__ void mma8(float* d, const uint32_t* a, uint32_t b0, uint32_t b1) {
    asm volatile(
        "mma.sync.aligned.m16n8k8.row.col.f32.tf32.tf32.f32 "
        "{%0,%1,%2,%3}, {%4,%5,%6,%7}, {%8,%9}, {%0,%1,%2,%3};\n"
        : "+f"(d[0]), "+f"(d[1]), "+f"(d[2]), "+f"(d[3])
        : "r"(a[0]), "r"(a[1]), "r"(a[2]), "r"(a[3]), "r"(b0), "r"(b1));
}

// ---------------------------------------------------------------------------
// Kernel 0: transform conv weights into B-fragment order (tf32-rounded).
// ---------------------------------------------------------------------------
__global__ __launch_bounds__(256) void wt_transform(const float* __restrict__ cw)
{
    int idx = blockIdx.x * 256 + threadIdx.x;
    if (idx >= 9 * 4096) return;
    int r    = idx & 1;
    int lane = (idx >> 1) & 31;
    int nt   = (idx >> 6) & 7;
    int kk   = (idx >> 9) & 7;
    int kidx = idx >> 12;
    int gid = lane >> 2, tig = lane & 3;
    int co = nt * 8 + gid;
    int ci = kk * 8 + tig + 4 * r;
    g_wt[idx] = f2tf32f(cw[(co * CIN + ci) * 9 + kidx]);
}

// ---------------------------------------------------------------------------
// Kernel 1: 3x3 conv (replication pad) via mma.sync tf32 implicit GEMM.
// (unchanged from 49.2us best)
// ---------------------------------------------------------------------------
#define SLAB_STRIDE 264
#define SLAB_FLOATS (64*SLAB_STRIDE)
#define BBUF_FLOATS 4096
#define DYN_SMEM ((SLAB_FLOATS + BBUF_FLOATS) * 4)

__global__ __launch_bounds__(256, 2) void conv_mma_kernel(
    const float* __restrict__ x, const float* __restrict__ cb)
{
    extern __shared__ float smem[];
    float* slab = smem;
    float* bbuf = smem + SLAB_FLOATS;

    const int tid  = threadIdx.x;
    const int lane = tid & 31;
    const int w    = tid >> 5;
    const int gid  = lane >> 2;
    const int tig  = lane & 3;
    const int wm   = (w & 3) * 32;
    const int wn   = (w >> 2) * 32;
    const int blk  = blockIdx.x;
    const int b    = blk >> 5;
    const int h0   = (blk & 31) * 2;

    const float* xb = x + (size_t)b * CTOT * HW;
    #pragma unroll
    for (int i = 0; i < 64; i++) {
        int idx = i * 256 + tid;
        int ci  = idx >> 8;
        int rc  = idx & 255;
        int rr  = rc >> 6;
        int col = rc & 63;
        int row = clampi(h0 - 1 + rr, 0, Hdim - 1);
        slab[ci * SLAB_STRIDE + rc] = f2tf32f(__ldg(xb + (ci * Hdim + row) * Wdim + col));
    }

    const float4* wt4 = (const float4*)g_wt;
    float4 pf[4];
    #pragma unroll
    for (int j = 0; j < 4; j++) pf[j] = __ldg(wt4 + j * 256 + tid);

    float acc[2][4][4];
    #pragma unroll
    for (int tm = 0; tm < 2; tm++)
        #pragma unroll
        for (int nt = 0; nt < 4; nt++)
            #pragma unroll
            for (int c = 0; c < 4; c++) acc[tm][nt][c] = 0.f;

    __syncthreads();

    int dy[2], col_lo[2], col_hi[2];
    #pragma unroll
    for (int tm = 0; tm < 2; tm++) {
        int pix = wm + tm * 16 + gid;
        dy[tm] = pix >> 6;
        col_lo[tm] = pix & 63;
        col_hi[tm] = col_lo[tm] + 8;
    }

    float4* bb4 = (float4*)bbuf;

    for (int kidx = 0; kidx < 9; kidx++) {
        const int ky = kidx / 3, kx = kidx % 3;
        if (kidx > 0) __syncthreads();
        #pragma unroll
        for (int j = 0; j < 4; j++) bb4[j * 256 + tid] = pf[j];
        __syncthreads();
        if (kidx < 8) {
            #pragma unroll
            for (int j = 0; j < 4; j++)
                pf[j] = __ldg(wt4 + (kidx + 1) * 1024 + j * 256 + tid);
        }

        int off_lo[2], off_hi[2];
        #pragma unroll
        for (int tm = 0; tm < 2; tm++) {
            int rowoff = (dy[tm] + ky) * 64;
            off_lo[tm] = rowoff + clampi(col_lo[tm] + kx - 1, 0, 63);
            off_hi[tm] = rowoff + clampi(col_hi[tm] + kx - 1, 0, 63);
        }

        #pragma unroll
        for (int kk = 0; kk < 8; kk++) {
            const int cib  = (kk * 8 + tig) * SLAB_STRIDE;
            const int cib4 = cib + 4 * SLAB_STRIDE;
            uint32_t a[2][4];
            #pragma unroll
            for (int tm = 0; tm < 2; tm++) {
                a[tm][0] = __float_as_uint(slab[cib  + off_lo[tm]]);
                a[tm][1] = __float_as_uint(slab[cib  + off_hi[tm]]);
                a[tm][2] = __float_as_uint(slab[cib4 + off_lo[tm]]);
                a[tm][3] = __float_as_uint(slab[cib4 + off_hi[tm]]);
            }
            #pragma unroll
            for (int nt = 0; nt < 4; nt++) {
                int ntg = (wn >> 3) + nt;
                float2 bf = *(const float2*)&bbuf[((kk * 8 + ntg) * 32 + lane) * 2];
                uint32_t b0 = __float_as_uint(bf.x);
                uint32_t b1 = __float_as_uint(bf.y);
                mma8(acc[0][nt], a[0], b0, b1);
                mma8(acc[1][nt], a[1], b0, b1);
            }
        }
    }

    #pragma unroll
    for (int tm = 0; tm < 2; tm++) {
        float* grow = g_conv + ((size_t)b * COUT * Hdim + (h0 + dy[tm])) * Wdim;
        #pragma unroll
        for (int nt = 0; nt < 4; nt++) {
            int co0 = wn + nt * 8 + 2 * tig;
            float b0 = __ldg(cb + co0), b1 = __ldg(cb + co0 + 1);
            grow[(size_t)co0       * HW + col_lo[tm]] = acc[tm][nt][0] + b0;
            grow[(size_t)(co0 + 1) * HW + col_lo[tm]] = acc[tm][nt][1] + b1;
            grow[(size_t)co0       * HW + col_hi[tm]] = acc[tm][nt][2] + b0;
            grow[(size_t)(co0 + 1) * HW + col_hi[tm]] = acc[tm][nt][3] + b1;
        }
    }
}

// ---------------------------------------------------------------------------
// Kernel 2: BN stats (unchanged)
// ---------------------------------------------------------------------------
__global__ __launch_bounds__(256) void bn_stats()
{
    __shared__ float ss[256], ss2[256];
    const int co = blockIdx.x;
    const int t  = threadIdx.x;
    float s = 0.f, s2 = 0.f;
    #pragma unroll
    for (int b = 0; b < BATCH; b++) {
        const float4* p = (const float4*)(g_conv + ((size_t)(b * COUT + co)) * HW);
        #pragma unroll
        for (int j = 0; j < 4; j++) {
            float4 v = __ldg(p + t + j * 256);
            s  += v.x + v.y + v.z + v.w;
            s2 += v.x * v.x + v.y * v.y + v.z * v.z + v.w * v.w;
        }
    }
    ss[t] = s; ss2[t] = s2;
    __syncthreads();
    for (int o = 128; o > 0; o >>= 1) {
        if (t < o) { ss[t] += ss[t + o]; ss2[t] += ss2[t + o]; }
        __syncthreads();
    }
    if (t == 0) {
        float n   = (float)(BATCH * HW);
        float mu  = ss[0] / n;
        float var = ss2[0] / n - mu * mu;
        g_mu[co] = mu;
        g_rs[co] = rsqrtf(var + 1e-5f);
    }
}

// ---------------------------------------------------------------------------
// Kernel 3: attend via 3xTF32 mma.sync. 64 pixels/block, 512 blocks.
// 256 threads / 8 warps: warp pair (w>>1) owns a 16-pixel strip (one m16
// tile); coHalf = w&1 owns 32 of 64 codes. A/B in smem as fp32; hi/lo tf32
// derived in registers. Softmax combined across the pair via smem partials.
// Final pass: quarter q owns 16 codes; sq combined via smem (deterministic).
// ---------------------------------------------------------------------------
#define A3_STRIDE 52
#define B3_STRIDE 72
#define SW3_STRIDE 66
#define AT3_A    0                        // [64][52] = 3328
#define AT3_B    (64*A3_STRIDE)           // 3328 ; [48][72] = 3456
#define AT3_REGION (AT3_B + 48*B3_STRIDE) // 6784 (overlay sW = 64*66 = 4224 fits)
#define AT3_REDM AT3_REGION               // [2][64]
#define AT3_REDS (AT3_REDM + 128)         // [2][64]
#define AT3_SQP  (AT3_REDS + 128)         // [4][64]
#define AT3_K2   (AT3_SQP + 256)          // [64]
#define AT3_MU   (AT3_K2 + 64)
#define AT3_RS   (AT3_MU + 64)
#define AT3_W2   (AT3_RS + 64)
#define AT3_FLOATS (AT3_W2 + 64)
#define AT3_DYN_SMEM (AT3_FLOATS * 4)     // ~30 KB

__global__ __launch_bounds__(256, 3) void attend_mma_kernel(
    const float* __restrict__ x, const float* __restrict__ sk,
    const float* __restrict__ c2w, const float* __restrict__ c2b,
    float* __restrict__ out)
{
    extern __shared__ float sm[];
    float* sA   = sm + AT3_A;
    float* sB   = sm + AT3_B;
    float* sW   = sm;                      // overlay after MMA
    float* sRm  = sm + AT3_REDM;
    float* sRs_ = sm + AT3_REDS;
    float* sSQP = sm + AT3_SQP;
    float* sK2  = sm + AT3_K2;
    float* sMu  = sm + AT3_MU;
    float* sRs  = sm + AT3_RS;
    float* sW2  = sm + AT3_W2;

    const int tid  = threadIdx.x;
    const int lane = tid & 31;
    const int warp = tid >> 5;
    const int gid  = lane >> 2;
    const int tig  = lane & 3;

    // ---- B setup: 2*codebook transposed [k][co], fp32; pad rows zero ----
    for (int i = tid; i < 64 * 45; i += 256) {
        int co = i / 45, t = i - co * 45;
        sB[t * B3_STRIDE + co] = 2.f * sk[i];
    }
    for (int i = tid; i < 3 * B3_STRIDE; i += 256) sB[45 * B3_STRIDE + i] = 0.f;
    if (tid < 64) {
        float a = 0.f;
        #pragma unroll
        for (int t = 0; t < 45; t++) {
            float kv = sk[tid * 45 + t];
            a = fmaf(kv, kv, a);
        }
        sK2[tid] = a;
        sMu[tid] = g_mu[tid];
        sRs[tid] = g_rs[tid];
        sW2[tid] = c2w[tid];
    }

    // ---- window build: quarter q handles channel subset for its pixel ----
    const int pix = tid & 63;
    const int q   = tid >> 6;
    const int p   = blockIdx.x * 64 + pix;
    const int b   = p >> 12;
    const int hw  = p & 4095;
    const int h   = hw >> 6;
    const int w   = hw & 63;

    if (q < 2) {
        // channels 0 / 1: center-subtract
        int c = q;
        float v[9];
        #pragma unroll
        for (int i = 0; i < 3; i++)
            #pragma unroll
            for (int j = 0; j < 3; j++) {
                int gy = clampi(h + i - 1, 0, Hdim - 1);
                int gx = clampi(w + j - 1, 0, Wdim - 1);
                v[i * 3 + j] = x[((b * CTOT + 64 + c) * Hdim + gy) * Wdim + gx];
            }
        float ctr = v[4];
        #pragma unroll
        for (int k = 0; k < 9; k++) sA[pix * A3_STRIDE + c * 9 + k] = v[k] - ctr;
        if (q == 0) {
            #pragma unroll
            for (int t = 45; t < 48; t++) sA[pix * A3_STRIDE + t] = 0.f;
        }
    } else if (q == 2) {
        #pragma unroll
        for (int c = 2; c < 4; c++)
            #pragma unroll
            for (int i = 0; i < 3; i++)
                #pragma unroll
                for (int j = 0; j < 3; j++) {
                    int gy = clampi(h + i - 1, 0, Hdim - 1);
                    int gx = clampi(w + j - 1, 0, Wdim - 1);
                    sA[pix * A3_STRIDE + c * 9 + i * 3 + j] =
                        x[((b * CTOT + 64 + c) * Hdim + gy) * Wdim + gx];
                }
    } else {
        #pragma unroll
        for (int i = 0; i < 3; i++)
            #pragma unroll
            for (int j = 0; j < 3; j++) {
                int gy = clampi(h + i - 1, 0, Hdim - 1);
                int gx = clampi(w + j - 1, 0, Wdim - 1);
                sA[pix * A3_STRIDE + 36 + i * 3 + j] =
                    x[((b * CTOT + 68) * Hdim + gy) * Wdim + gx];
            }
    }
    __syncthreads();

    // ---- MMA: warp pair (warp>>1) -> 16-row strip; coHalf = warp&1 ----
    const int rstrip = (warp >> 1) * 16;
    const int coHalf = warp & 1;
    const int nt0    = coHalf * 4;

    float acc[4][4];
    #pragma unroll
    for (int nt = 0; nt < 4; nt++)
        #pragma unroll
        for (int c = 0; c < 4; c++) acc[nt][c] = 0.f;

    #pragma unroll
    for (int ks = 0; ks < 6; ks++) {
        uint32_t ah[4], al[4];
        {
            int r0 = rstrip + gid;
            float o0 = sA[r0 * A3_STRIDE + ks * 8 + tig];
            float o1 = sA[(r0 + 8) * A3_STRIDE + ks * 8 + tig];
            float o2 = sA[r0 * A3_STRIDE + ks * 8 + tig + 4];
            float o3 = sA[(r0 + 8) * A3_STRIDE + ks * 8 + tig + 4];
            float h0 = f2tf32f(o0), h1 = f2tf32f(o1), h2 = f2tf32f(o2), h3 = f2tf32f(o3);
            ah[0] = __float_as_uint(h0); al[0] = __float_as_uint(f2tf32f(o0 - h0));
            ah[1] = __float_as_uint(h1); al[1] = __float_as_uint(f2tf32f(o1 - h1));
            ah[2] = __float_as_uint(h2); al[2] = __float_as_uint(f2tf32f(o2 - h2));
            ah[3] = __float_as_uint(h3); al[3] = __float_as_uint(f2tf32f(o3 - h3));
        }
        #pragma unroll
        for (int ntl = 0; ntl < 4; ntl++) {
            int nt = nt0 + ntl;
            float bo0 = sB[(ks * 8 + tig) * B3_STRIDE + nt * 8 + gid];
            float bo1 = sB[(ks * 8 + tig + 4) * B3_STRIDE + nt * 8 + gid];
            float bh0 = f2tf32f(bo0), bh1 = f2tf32f(bo1);
            uint32_t uh0 = __float_as_uint(bh0), uh1 = __float_as_uint(bh1);
            uint32_t ul0 = __float_as_uint(f2tf32f(bo0 - bh0));
            uint32_t ul1 = __float_as_uint(f2tf32f(bo1 - bh1));
            mma8(acc[ntl], ah, uh0, uh1);
            mma8(acc[ntl], al, uh0, uh1);
            mma8(acc[ntl], ah, ul0, ul1);
        }
    }
    __syncthreads();   // all A/B reads done (before sW overlay writes)

    // ---- softmax phase 1: logits & per-warp partial max ----
    #pragma unroll
    for (int h8 = 0; h8 < 2; h8++) {
        float m = -3.4e38f;
        #pragma unroll
        for (int ntl = 0; ntl < 4; ntl++) {
            #pragma unroll
            for (int cc = 0; cc < 2; cc++) {
                int co = coHalf * 32 + ntl * 8 + 2 * tig + cc;
                float l = acc[ntl][2 * h8 + cc] - sK2[co];
                acc[ntl][2 * h8 + cc] = l;
                m = fmaxf(m, l);
            }
        }
        m = fmaxf(m, __shfl_xor_sync(0xffffffffu, m, 1));
        m = fmaxf(m, __shfl_xor_sync(0xffffffffu, m, 2));
        if (tig == 0) sRm[coHalf * 64 + rstrip + gid + 8 * h8] = m;
    }
    __syncthreads();

    // ---- phase 2: combined max, exp, partial sums ----
    #pragma unroll
    for (int h8 = 0; h8 < 2; h8++) {
        int row = rstrip + gid + 8 * h8;
        float m = fmaxf(sRm[row], sRm[64 + row]);
        float s = 0.f;
        #pragma unroll
        for (int ntl = 0; ntl < 4; ntl++) {
            #pragma unroll
            for (int cc = 0; cc < 2; cc++) {
                float e = __expf(acc[ntl][2 * h8 + cc] - m);
                acc[ntl][2 * h8 + cc] = e;
                s += e;
            }
        }
        s += __shfl_xor_sync(0xffffffffu, s, 1);
        s += __shfl_xor_sync(0xffffffffu, s, 2);
        if (tig == 0) sRs_[coHalf * 64 + row] = s;
    }
    __syncthreads();

    // ---- phase 3: normalize & transpose into sW[co][row] ----
    #pragma unroll
    for (int h8 = 0; h8 < 2; h8++) {
        int row = rstrip + gid + 8 * h8;
        float inv = 1.f / (sRs_[row] + sRs_[64 + row]);
        #pragma unroll
        for (int ntl = 0; ntl < 4; ntl++) {
            #pragma unroll
            for (int cc = 0; cc < 2; cc++) {
                int co = coHalf * 32 + ntl * 8 + 2 * tig + cc;
                sW[co * SW3_STRIDE + row] = acc[ntl][2 * h8 + cc] * inv;
            }
        }
    }
    __syncthreads();

    // ---- final coalesced pass: quarter q owns 16 codes ----
    const float* gc = g_conv + (size_t)b * COUT * HW + hw;
    float* op = out + (size_t)b * CTOT * HW + hw;
    float sq = 0.f;
    const int cb0 = q * 16;
    #pragma unroll
    for (int j = 0; j < 16; j++) {
        int co = cb0 + j;
        float ww  = sW[co * SW3_STRIDE + pix];
        float cv  = (gc[(size_t)co * HW] - sMu[co]) * sRs[co];
        float att = fmaxf(cv * ww, 0.f);
        op[(size_t)co * HW] = att;
        sq = fmaf(sW2[co], att, sq);
    }
    sSQP[q * 64 + pix] = sq;
    __syncthreads();
    if (q == 0)
        g_sq[p] = sSQP[pix] + sSQP[64 + pix] + sSQP[128 + pix] + sSQP[192 + pix]
                + __ldg(c2b);
}

// ---------------------------------------------------------------------------
// Kernel 4: window softmax of shape query (zero-padded) + weighted stats
// ---------------------------------------------------------------------------
__global__ __launch_bounds__(256) void agg_kernel(
    const float* __restrict__ x, float* __restrict__ out)
{
    const int p = blockIdx.x * 256 + threadIdx.x;
    if (p >= NPIX) return;
    const int b  = p >> 12;
    const int hw = p & 4095;
    const int h  = hw >> 6;
    const int w  = hw & 63;

    float qv[9];
    float qmax = -3.4e38f;
    #pragma unroll
    for (int i = 0; i < 3; i++)
        #pragma unroll
        for (int j = 0; j < 3; j++) {
            int yy = h + i - 1, xx = w + j - 1;
            float v = 0.f;
            if (yy >= 0 && yy < Hdim && xx >= 0 && xx < Wdim)
                v = g_sq[(b << 12) + (yy << 6) + xx];
            qv[i * 3 + j] = v;
            qmax = fmaxf(qmax, v);
        }
    float qs = 0.f;
    #pragma unroll
    for (int k = 0; k < 9; k++) { qv[k] = __expf(qv[k] - qmax); qs += qv[k]; }
    float qinv = 1.f / qs;
    #pragma unroll
    for (int k = 0; k < 9; k++) qv[k] *= qinv;

    float win[5][9];
    #pragma unroll
    for (int c = 0; c < 5; c++) {
        #pragma unroll
        for (int i = 0; i < 3; i++)
            #pragma unroll
            for (int j = 0; j < 3; j++) {
                int gy = clampi(h + i - 1, 0, Hdim - 1);
                int gx = clampi(w + j - 1, 0, Wdim - 1);
                win[c][i * 3 + j] = x[((b * CTOT + 64 + c) * Hdim + gy) * Wdim + gx];
            }
    }

    float mean0 = 0.f, mean1 = 0.f, v1_0 = 0.f, v1_1 = 0.f, c1 = 0.f;
    #pragma unroll
    for (int k = 0; k < 9; k++) {
        mean0 = fmaf(win[0][k], qv[k], mean0);
        mean1 = fmaf(win[1][k], qv[k], mean1);
        v1_0  = fmaf(win[2][k], qv[k], v1_0);
        v1_1  = fmaf(win[3][k], qv[k], v1_1);
        c1    = fmaf(win[4][k], qv[k], c1);
    }
    float v2_0 = 0.f, v2_1 = 0.f, c2 = 0.f;
    #pragma unroll
    for (int k = 0; k < 9; k++) {
        float d0 = win[0][k] - mean0;
        float d1 = win[1][k] - mean1;
        v2_0 = fmaf(d0 * d0, qv[k], v2_0);
        v2_1 = fmaf(d1 * d1, qv[k], v2_1);
        c2   = fmaf(d0 * d1, qv[k], c2);
    }

    out[((b * CTOT + 64) * Hdim + h) * Wdim + w] = mean0;
    out[((b * CTOT + 65) * Hdim + h) * Wdim + w] = mean1;
    out[((b * CTOT + 66) * Hdim + h) * Wdim + w] = v1_0 + v2_0;
    out[((b * CTOT + 67) * Hdim + h) * Wdim + w] = v1_1 + v2_1;
    out[((b * CTOT + 68) * Hdim + h) * Wdim + w] = c1 + c2;
}

// ---------------------------------------------------------------------------
extern "C" void kernel_launch(void* const* d_in, const int* in_sizes, int n_in,
                              void* d_out, int out_size)
{
    const float* x   = (const float*)d_in[0];
    const float* cw  = (const float*)d_in[1];
    const float* cb  = (const float*)d_in[2];
    const float* c2w = (const float*)d_in[3];
    const float* c2b = (const float*)d_in[4];
    const float* sk  = (const float*)d_in[5];
    float* out = (float*)d_out;

    static bool attr_set = false;
    if (!attr_set) {
        cudaFuncSetAttribute(conv_mma_kernel,
                             cudaFuncAttributeMaxDynamicSharedMemorySize, DYN_SMEM);
        cudaFuncSetAttribute(attend_mma_kernel,
                             cudaFuncAttributeMaxDynamicSharedMemorySize, AT3_DYN_SMEM);
        attr_set = true;
    }

    wt_transform<<<144, 256>>>(cw);
    conv_mma_kernel<<<256, 256, DYN_SMEM>>>(x, cb);
    bn_stats<<<64, 256>>>();
    attend_mma_kernel<<<NPIX / 64, 256, AT3_DYN_SMEM>>>(x, sk, c2w, c2b, out);
    agg_kernel<<<NPIX / 256, 256>>>(x, out);
}

// round 13
// speedup vs baseline: 1.0923x; 1.0923x over previous
#include <cuda_runtime.h>
#include <cstdint>

#define BATCH 8
#define CIN   64
#define COUT  64
#define Hdim  64
#define Wdim  64
#define CTOT  69
#define HW    (Hdim*Wdim)
#define NPIX  (BATCH*HW)

// Scratch (static device globals — no allocation)
__device__ float g_conv[BATCH*COUT*HW];   // raw conv output (pre-BN)
__device__ float g_sq[NPIX];              // 1x1-conv "shape query"
__device__ float g_mu[COUT];
__device__ float g_rs[COUT];
__device__ float g_psum[COUT*256];        // per-(co, conv-block) partials
__device__ float g_psumsq[COUT*256];
__device__ __align__(16) float g_wt[9*4096];   // conv weights, B-fragment order
__device__ __align__(16) float g_bhi[48*72];   // codebook 2k hi, [t][co]
__device__ __align__(16) float g_blo[48*72];   // codebook 2k lo
__device__ float g_k2v[64];                    // |k|^2 per code

__device__ __forceinline__ int clampi(int v, int lo, int hi) {
    return v < lo ? lo : (v > hi ? hi : v);
}
__device__ __forceinline__ float f2tf32f(float f) {
    uint32_t r; asm("cvt.rna.tf32.f32 %0, %1;" : "=r"(r) : "f"(f));
    return __uint_as_float(r);
}

// m16n8k8 tf32 mma: D += A*B (D==C, fp32 accum). a: 4 regs, b: 2 regs.
__device__ __forceinline__ void mma8(float* d, const uint32_t* a, uint32_t b0, uint32_t b1) {
    asm volatile(
        "mma.sync.aligned.m16n8k8.row.col.f32.tf32.tf32.f32 "
        "{%0,%1,%2,%3}, {%4,%5,%6,%7}, {%8,%9}, {%0,%1,%2,%3};\n"
        : "+f"(d[0]), "+f"(d[1]), "+f"(d[2]), "+f"(d[3])
        : "r"(a[0]), "r"(a[1]), "r"(a[2]), "r"(a[3]), "r"(b0), "r"(b1));
}

// ---------------------------------------------------------------------------
// Kernel 0: prep — conv weight fragment transform + codebook hi/lo + |k|^2
// ---------------------------------------------------------------------------
#define PREP_WT   (9*4096)            // 36864
#define PREP_B    (48*72)             // 3456
#define PREP_TOT  (PREP_WT + PREP_B + 64)

__global__ __launch_bounds__(256) void prep_kernel(
    const float* __restrict__ cw, const float* __restrict__ sk)
{
    int idx = blockIdx.x * 256 + threadIdx.x;
    if (idx < PREP_WT) {
        int r    = idx & 1;
        int lane = (idx >> 1) & 31;
        int nt   = (idx >> 6) & 7;
        int kk   = (idx >> 9) & 7;
        int kidx = idx >> 12;
        int gid = lane >> 2, tig = lane & 3;
        int co = nt * 8 + gid;
        int ci = kk * 8 + tig + 4 * r;
        g_wt[idx] = f2tf32f(cw[(co * CIN + ci) * 9 + kidx]);
    } else if (idx < PREP_WT + PREP_B) {
        int i  = idx - PREP_WT;
        int t  = i / 72;
        int co = i - t * 72;
        float val = (co < 64 && t < 45) ? 2.f * sk[co * 45 + t] : 0.f;
        float hi  = f2tf32f(val);
        g_bhi[i] = hi;
        g_blo[i] = f2tf32f(val - hi);
    } else if (idx < PREP_TOT) {
        int co = idx - PREP_WT - PREP_B;
        float a = 0.f;
        for (int t = 0; t < 45; t++) {
            float kv = sk[co * 45 + t];
            a = fmaf(kv, kv, a);
        }
        g_k2v[co] = a;
    }
}

// ---------------------------------------------------------------------------
// Kernel 1: 3x3 conv (replication pad) via mma.sync tf32 implicit GEMM,
// now with fused BN partial sums in the epilogue (deterministic order).
// ---------------------------------------------------------------------------
#define SLAB_STRIDE 264
#define SLAB_FLOATS (64*SLAB_STRIDE)
#define BBUF_FLOATS 4096
#define DYN_SMEM ((SLAB_FLOATS + BBUF_FLOATS) * 4)

__global__ __launch_bounds__(256, 2) void conv_mma_kernel(
    const float* __restrict__ x, const float* __restrict__ cb)
{
    extern __shared__ float smem[];
    float* slab = smem;
    float* bbuf = smem + SLAB_FLOATS;

    const int tid  = threadIdx.x;
    const int lane = tid & 31;
    const int w    = tid >> 5;
    const int gid  = lane >> 2;
    const int tig  = lane & 3;
    const int wm   = (w & 3) * 32;
    const int wn   = (w >> 2) * 32;
    const int blk  = blockIdx.x;
    const int b    = blk >> 5;
    const int h0   = (blk & 31) * 2;

    const float* xb = x + (size_t)b * CTOT * HW;
    #pragma unroll
    for (int i = 0; i < 64; i++) {
        int idx = i * 256 + tid;
        int ci  = idx >> 8;
        int rc  = idx & 255;
        int rr  = rc >> 6;
        int col = rc & 63;
        int row = clampi(h0 - 1 + rr, 0, Hdim - 1);
        slab[ci * SLAB_STRIDE + rc] = f2tf32f(__ldg(xb + (ci * Hdim + row) * Wdim + col));
    }

    const float4* wt4 = (const float4*)g_wt;
    float4 pf[4];
    #pragma unroll
    for (int j = 0; j < 4; j++) pf[j] = __ldg(wt4 + j * 256 + tid);

    float acc[2][4][4];
    #pragma unroll
    for (int tm = 0; tm < 2; tm++)
        #pragma unroll
        for (int nt = 0; nt < 4; nt++)
            #pragma unroll
            for (int c = 0; c < 4; c++) acc[tm][nt][c] = 0.f;

    __syncthreads();

    int dy[2], col_lo[2], col_hi[2];
    #pragma unroll
    for (int tm = 0; tm < 2; tm++) {
        int pix = wm + tm * 16 + gid;
        dy[tm] = pix >> 6;
        col_lo[tm] = pix & 63;
        col_hi[tm] = col_lo[tm] + 8;
    }

    float4* bb4 = (float4*)bbuf;

    for (int kidx = 0; kidx < 9; kidx++) {
        const int ky = kidx / 3, kx = kidx % 3;
        if (kidx > 0) __syncthreads();
        #pragma unroll
        for (int j = 0; j < 4; j++) bb4[j * 256 + tid] = pf[j];
        __syncthreads();
        if (kidx < 8) {
            #pragma unroll
            for (int j = 0; j < 4; j++)
                pf[j] = __ldg(wt4 + (kidx + 1) * 1024 + j * 256 + tid);
        }

        int off_lo[2], off_hi[2];
        #pragma unroll
        for (int tm = 0; tm < 2; tm++) {
            int rowoff = (dy[tm] + ky) * 64;
            off_lo[tm] = rowoff + clampi(col_lo[tm] + kx - 1, 0, 63);
            off_hi[tm] = rowoff + clampi(col_hi[tm] + kx - 1, 0, 63);
        }

        #pragma unroll
        for (int kk = 0; kk < 8; kk++) {
            const int cib  = (kk * 8 + tig) * SLAB_STRIDE;
            const int cib4 = cib + 4 * SLAB_STRIDE;
            uint32_t a[2][4];
            #pragma unroll
            for (int tm = 0; tm < 2; tm++) {
                a[tm][0] = __float_as_uint(slab[cib  + off_lo[tm]]);
                a[tm][1] = __float_as_uint(slab[cib  + off_hi[tm]]);
                a[tm][2] = __float_as_uint(slab[cib4 + off_lo[tm]]);
                a[tm][3] = __float_as_uint(slab[cib4 + off_hi[tm]]);
            }
            #pragma unroll
            for (int nt = 0; nt < 4; nt++) {
                int ntg = (wn >> 3) + nt;
                float2 bf = *(const float2*)&bbuf[((kk * 8 + ntg) * 32 + lane) * 2];
                uint32_t b0 = __float_as_uint(bf.x);
                uint32_t b1 = __float_as_uint(bf.y);
                mma8(acc[0][nt], a[0], b0, b1);
                mma8(acc[1][nt], a[1], b0, b1);
            }
        }
    }

    // ---- epilogue: +bias, write g_conv, accumulate BN partials ----
    float ps[4][2], ps2[4][2];
    #pragma unroll
    for (int nt = 0; nt < 4; nt++) {
        ps[nt][0] = ps[nt][1] = 0.f;
        ps2[nt][0] = ps2[nt][1] = 0.f;
    }
    #pragma unroll
    for (int tm = 0; tm < 2; tm++) {
        float* grow = g_conv + ((size_t)b * COUT * Hdim + (h0 + dy[tm])) * Wdim;
        #pragma unroll
        for (int nt = 0; nt < 4; nt++) {
            int co0 = wn + nt * 8 + 2 * tig;
            float b0 = __ldg(cb + co0), b1 = __ldg(cb + co0 + 1);
            float v0 = acc[tm][nt][0] + b0;
            float v1 = acc[tm][nt][1] + b1;
            float v2 = acc[tm][nt][2] + b0;
            float v3 = acc[tm][nt][3] + b1;
            grow[(size_t)co0       * HW + col_lo[tm]] = v0;
            grow[(size_t)(co0 + 1) * HW + col_lo[tm]] = v1;
            grow[(size_t)co0       * HW + col_hi[tm]] = v2;
            grow[(size_t)(co0 + 1) * HW + col_hi[tm]] = v3;
            ps[nt][0]  += v0 + v2;
            ps2[nt][0] += v0 * v0 + v2 * v2;
            ps[nt][1]  += v1 + v3;
            ps2[nt][1] += v1 * v1 + v3 * v3;
        }
    }

    __syncthreads();              // slab/bbuf dead -> overlay reduction area
    float* sred = smem;           // [8 warps][64] : [0:32)=s, [32:64)=s2
    #pragma unroll
    for (int nt = 0; nt < 4; nt++) {
        #pragma unroll
        for (int cc = 0; cc < 2; cc++) {
            float s = ps[nt][cc], s2 = ps2[nt][cc];
            s  += __shfl_xor_sync(0xffffffffu, s,  4);
            s  += __shfl_xor_sync(0xffffffffu, s,  8);
            s  += __shfl_xor_sync(0xffffffffu, s, 16);
            s2 += __shfl_xor_sync(0xffffffffu, s2,  4);
            s2 += __shfl_xor_sync(0xffffffffu, s2,  8);
            s2 += __shfl_xor_sync(0xffffffffu, s2, 16);
            if (gid == 0) {
                int ci = nt * 8 + 2 * tig + cc;
                sred[w * 64 + ci]      = s;
                sred[w * 64 + 32 + ci] = s2;
            }
        }
    }
    __syncthreads();
    if (tid < 64) {
        int co = tid;
        int wb = (co >> 5) * 4;      // warps 0-3 hold co 0..31, warps 4-7 hold 32..63
        int cl = co & 31;
        float s = 0.f, s2 = 0.f;
        #pragma unroll
        for (int i = 0; i < 4; i++) {
            s  += sred[(wb + i) * 64 + cl];
            s2 += sred[(wb + i) * 64 + 32 + cl];
        }
        g_psum[co * 256 + blk]   = s;
        g_psumsq[co * 256 + blk] = s2;
    }
}

// ---------------------------------------------------------------------------
// Kernel 2: BN finalize — reduce 256 partials per channel (deterministic)
// ---------------------------------------------------------------------------
__global__ __launch_bounds__(256) void bn_finalize()
{
    __shared__ float ss[256], ss2[256];
    const int co = blockIdx.x;
    const int t  = threadIdx.x;
    ss[t]  = g_psum[co * 256 + t];
    ss2[t] = g_psumsq[co * 256 + t];
    __syncthreads();
    for (int o = 128; o > 0; o >>= 1) {
        if (t < o) { ss[t] += ss[t + o]; ss2[t] += ss2[t + o]; }
        __syncthreads();
    }
    if (t == 0) {
        float n   = (float)(BATCH * HW);
        float mu  = ss[0] / n;
        float var = ss2[0] / n - mu * mu;
        g_mu[co] = mu;
        g_rs[co] = rsqrtf(var + 1e-5f);
    }
}

// ---------------------------------------------------------------------------
// Kernel 3: attend via 3xTF32 mma.sync. 64 pixels/block, 512 blocks.
// All tf32 hi/lo conversions hoisted OUT of the MMA loop: B hi/lo precomputed
// globally (prep_kernel), A hi/lo split once at window-build time.
// Inner loop is pure LDS + MMA.
// ---------------------------------------------------------------------------
#define A3_STRIDE 52
#define B3_STRIDE 72
#define SW3_STRIDE 66
#define AT3_AHI  0                          // [64][52] = 3328
#define AT3_ALO  (64*A3_STRIDE)             // 3328
#define AT3_BHI  (2*64*A3_STRIDE)           // 6656 ; [48][72] = 3456
#define AT3_BLO  (AT3_BHI + 48*B3_STRIDE)   // 10112
#define AT3_REGION (AT3_BLO + 48*B3_STRIDE) // 13568 (overlay sW = 4224 fits)
#define AT3_REDM AT3_REGION                 // [2][64]
#define AT3_REDS (AT3_REDM + 128)           // [2][64]
#define AT3_SQP  (AT3_REDS + 128)           // [4][64]
#define AT3_K2   (AT3_SQP + 256)            // [64]
#define AT3_MU   (AT3_K2 + 64)
#define AT3_RS   (AT3_MU + 64)
#define AT3_W2   (AT3_RS + 64)
#define AT3_FLOATS (AT3_W2 + 64)
#define AT3_DYN_SMEM (AT3_FLOATS * 4)       // ~57 KB

__global__ __launch_bounds__(256, 3) void attend_mma_kernel(
    const float* __restrict__ x,
    const float* __restrict__ c2w, const float* __restrict__ c2b,
    float* __restrict__ out)
{
    extern __shared__ float sm[];
    float* sAhi = sm + AT3_AHI;
    float* sAlo = sm + AT3_ALO;
    float* sBhi = sm + AT3_BHI;
    float* sBlo = sm + AT3_BLO;
    float* sW   = sm;                      // overlay after MMA
    float* sRm  = sm + AT3_REDM;
    float* sRs_ = sm + AT3_REDS;
    float* sSQP = sm + AT3_SQP;
    float* sK2  = sm + AT3_K2;
    float* sMu  = sm + AT3_MU;
    float* sRs  = sm + AT3_RS;
    float* sW2  = sm + AT3_W2;

    const int tid  = threadIdx.x;
    const int lane = tid & 31;
    const int warp = tid >> 5;
    const int gid  = lane >> 2;
    const int tig  = lane & 3;

    // ---- copy precomputed B hi/lo (coalesced float4) + constants ----
    {
        const float4* bh4 = (const float4*)g_bhi;
        const float4* bl4 = (const float4*)g_blo;
        float4* dh4 = (float4*)sBhi;
        float4* dl4 = (float4*)sBlo;
        #pragma unroll
        for (int i = tid; i < (48 * B3_STRIDE) / 4; i += 256) {
            dh4[i] = __ldg(bh4 + i);
            dl4[i] = __ldg(bl4 + i);
        }
    }
    if (tid < 64) {
        sK2[tid] = g_k2v[tid];
        sMu[tid] = g_mu[tid];
        sRs[tid] = g_rs[tid];
        sW2[tid] = c2w[tid];
    }

    // ---- window build: quarter q handles channel subset for its pixel ----
    const int pix = tid & 63;
    const int q   = tid >> 6;
    const int p   = blockIdx.x * 64 + pix;
    const int b   = p >> 12;
    const int hw  = p & 4095;
    const int h   = hw >> 6;
    const int w   = hw & 63;

    if (q < 2) {
        int c = q;
        float v[9];
        #pragma unroll
        for (int i = 0; i < 3; i++)
            #pragma unroll
            for (int j = 0; j < 3; j++) {
                int gy = clampi(h + i - 1, 0, Hdim - 1);
                int gx = clampi(w + j - 1, 0, Wdim - 1);
                v[i * 3 + j] = x[((b * CTOT + 64 + c) * Hdim + gy) * Wdim + gx];
            }
        float ctr = v[4];
        #pragma unroll
        for (int k = 0; k < 9; k++) {
            float val = v[k] - ctr;
            float hi  = f2tf32f(val);
            sAhi[pix * A3_STRIDE + c * 9 + k] = hi;
            sAlo[pix * A3_STRIDE + c * 9 + k] = f2tf32f(val - hi);
        }
        if (q == 0) {
            #pragma unroll
            for (int t = 45; t < 48; t++) {
                sAhi[pix * A3_STRIDE + t] = 0.f;
                sAlo[pix * A3_STRIDE + t] = 0.f;
            }
        }
    } else if (q == 2) {
        #pragma unroll
        for (int c = 2; c < 4; c++)
            #pragma unroll
            for (int i = 0; i < 3; i++)
                #pragma unroll
                for (int j = 0; j < 3; j++) {
                    int gy = clampi(h + i - 1, 0, Hdim - 1);
                    int gx = clampi(w + j - 1, 0, Wdim - 1);
                    float val = x[((b * CTOT + 64 + c) * Hdim + gy) * Wdim + gx];
                    float hi  = f2tf32f(val);
                    sAhi[pix * A3_STRIDE + c * 9 + i * 3 + j] = hi;
                    sAlo[pix * A3_STRIDE + c * 9 + i * 3 + j] = f2tf32f(val - hi);
                }
    } else {
        #pragma unroll
        for (int i = 0; i < 3; i++)
            #pragma unroll
            for (int j = 0; j < 3; j++) {
                int gy = clampi(h + i - 1, 0, Hdim - 1);
                int gx = clampi(w + j - 1, 0, Wdim - 1);
                float val = x[((b * CTOT + 68) * Hdim + gy) * Wdim + gx];
                float hi  = f2tf32f(val);
                sAhi[pix * A3_STRIDE + 36 + i * 3 + j] = hi;
                sAlo[pix * A3_STRIDE + 36 + i * 3 + j] = f2tf32f(val - hi);
            }
    }
    __syncthreads();

    // ---- MMA: warp pair (warp>>1) -> 16-row strip; coHalf = warp&1 ----
    const int rstrip = (warp >> 1) * 16;
    const int coHalf = warp & 1;
    const int nt0    = coHalf * 4;

    float acc[4][4];
    #pragma unroll
    for (int nt = 0; nt < 4; nt++)
        #pragma unroll
        for (int c = 0; c < 4; c++) acc[nt][c] = 0.f;

    #pragma unroll
    for (int ks = 0; ks < 6; ks++) {
        uint32_t ah[4], al[4];
        {
            int r0 = rstrip + gid;
            int o  = ks * 8 + tig;
            ah[0] = __float_as_uint(sAhi[r0 * A3_STRIDE + o]);
            ah[1] = __float_as_uint(sAhi[(r0 + 8) * A3_STRIDE + o]);
            ah[2] = __float_as_uint(sAhi[r0 * A3_STRIDE + o + 4]);
            ah[3] = __float_as_uint(sAhi[(r0 + 8) * A3_STRIDE + o + 4]);
            al[0] = __float_as_uint(sAlo[r0 * A3_STRIDE + o]);
            al[1] = __float_as_uint(sAlo[(r0 + 8) * A3_STRIDE + o]);
            al[2] = __float_as_uint(sAlo[r0 * A3_STRIDE + o + 4]);
            al[3] = __float_as_uint(sAlo[(r0 + 8) * A3_STRIDE + o + 4]);
        }
        #pragma unroll
        for (int ntl = 0; ntl < 4; ntl++) {
            int nt = nt0 + ntl;
            int r1 = (ks * 8 + tig) * B3_STRIDE + nt * 8 + gid;
            int r2 = (ks * 8 + tig + 4) * B3_STRIDE + nt * 8 + gid;
            uint32_t uh0 = __float_as_uint(sBhi[r1]);
            uint32_t uh1 = __float_as_uint(sBhi[r2]);
            uint32_t ul0 = __float_as_uint(sBlo[r1]);
            uint32_t ul1 = __float_as_uint(sBlo[r2]);
            mma8(acc[ntl], ah, uh0, uh1);
            mma8(acc[ntl], al, uh0, uh1);
            mma8(acc[ntl], ah, ul0, ul1);
        }
    }
    __syncthreads();   // all A/B reads done (before sW overlay writes)

    // ---- softmax phase 1: logits & per-warp partial max ----
    #pragma unroll
    for (int h8 = 0; h8 < 2; h8++) {
        float m = -3.4e38f;
        #pragma unroll
        for (int ntl = 0; ntl < 4; ntl++) {
            #pragma unroll
            for (int cc = 0; cc < 2; cc++) {
                int co = coHalf * 32 + ntl * 8 + 2 * tig + cc;
                float l = acc[ntl][2 * h8 + cc] - sK2[co];
                acc[ntl][2 * h8 + cc] = l;
                m = fmaxf(m, l);
            }
        }
        m = fmaxf(m, __shfl_xor_sync(0xffffffffu, m, 1));
        m = fmaxf(m, __shfl_xor_sync(0xffffffffu, m, 2));
        if (tig == 0) sRm[coHalf * 64 + rstrip + gid + 8 * h8] = m;
    }
    __syncthreads();

    // ---- phase 2: combined max, exp, partial sums ----
    #pragma unroll
    for (int h8 = 0; h8 < 2; h8++) {
        int row = rstrip + gid + 8 * h8;
        float m = fmaxf(sRm[row], sRm[64 + row]);
        float s = 0.f;
        #pragma unroll
        for (int ntl = 0; ntl < 4; ntl++) {
            #pragma unroll
            for (int cc = 0; cc < 2; cc++) {
                float e = __expf(acc[ntl][2 * h8 + cc] - m);
                acc[ntl][2 * h8 + cc] = e;
                s += e;
            }
        }
        s += __shfl_xor_sync(0xffffffffu, s, 1);
        s += __shfl_xor_sync(0xffffffffu, s, 2);
        if (tig == 0) sRs_[coHalf * 64 + row] = s;
    }
    __syncthreads();

    // ---- phase 3: normalize & transpose into sW[co][row] ----
    #pragma unroll
    for (int h8 = 0; h8 < 2; h8++) {
        int row = rstrip + gid + 8 * h8;
        float inv = 1.f / (sRs_[row] + sRs_[64 + row]);
        #pragma unroll
        for (int ntl = 0; ntl < 4; ntl++) {
            #pragma unroll
            for (int cc = 0; cc < 2; cc++) {
                int co = coHalf * 32 + ntl * 8 + 2 * tig + cc;
                sW[co * SW3_STRIDE + row] = acc[ntl][2 * h8 + cc] * inv;
            }
        }
    }
    __syncthreads();

    // ---- final coalesced pass: quarter q owns 16 codes ----
    const float* gc = g_conv + (size_t)b * COUT * HW + hw;
    float* op = out + (size_t)b * CTOT * HW + hw;
    float sq = 0.f;
    const int cb0 = q * 16;
    #pragma unroll
    for (int j = 0; j < 16; j++) {
        int co = cb0 + j;
        float ww  = sW[co * SW3_STRIDE + pix];
        float cv  = (gc[(size_t)co * HW] - sMu[co]) * sRs[co];
        float att = fmaxf(cv * ww, 0.f);
        op[(size_t)co * HW] = att;
        sq = fmaf(sW2[co], att, sq);
    }
    sSQP[q * 64 + pix] = sq;
    __syncthreads();
    if (q == 0)
        g_sq[p] = sSQP[pix] + sSQP[64 + pix] + sSQP[128 + pix] + sSQP[192 + pix]
                + __ldg(c2b);
}

// ---------------------------------------------------------------------------
// Kernel 4: window softmax of shape query (zero-padded) + weighted stats
// ---------------------------------------------------------------------------
__global__ __launch_bounds__(256) void agg_kernel(
    const float* __restrict__ x, float* __restrict__ out)
{
    const int p = blockIdx.x * 256 + threadIdx.x;
    if (p >= NPIX) return;
    const int b  = p >> 12;
    const int hw = p & 4095;
    const int h  = hw >> 6;
    const int w  = hw & 63;

    float qv[9];
    float qmax = -3.4e38f;
    #pragma unroll
    for (int i = 0; i < 3; i++)
        #pragma unroll
        for (int j = 0; j < 3; j++) {
            int yy = h + i - 1, xx = w + j - 1;
            float v = 0.f;
            if (yy >= 0 && yy < Hdim && xx >= 0 && xx < Wdim)
                v = g_sq[(b << 12) + (yy << 6) + xx];
            qv[i * 3 + j] = v;
            qmax = fmaxf(qmax, v);
        }
    float qs = 0.f;
    #pragma unroll
    for (int k = 0; k < 9; k++) { qv[k] = __expf(qv[k] - qmax); qs += qv[k]; }
    float qinv = 1.f / qs;
    #pragma unroll
    for (int k = 0; k < 9; k++) qv[k] *= qinv;

    float win[5][9];
    #pragma unroll
    for (int c = 0; c < 5; c++) {
        #pragma unroll
        for (int i = 0; i < 3; i++)
            #pragma unroll
            for (int j = 0; j < 3; j++) {
                int gy = clampi(h + i - 1, 0, Hdim - 1);
                int gx = clampi(w + j - 1, 0, Wdim - 1);
                win[c][i * 3 + j] = x[((b * CTOT + 64 + c) * Hdim + gy) * Wdim + gx];
            }
    }

    float mean0 = 0.f, mean1 = 0.f, v1_0 = 0.f, v1_1 = 0.f, c1 = 0.f;
    #pragma unroll
    for (int k = 0; k < 9; k++) {
        mean0 = fmaf(win[0][k], qv[k], mean0);
        mean1 = fmaf(win[1][k], qv[k], mean1);
        v1_0  = fmaf(win[2][k], qv[k], v1_0);
        v1_1  = fmaf(win[3][k], qv[k], v1_1);
        c1    = fmaf(win[4][k], qv[k], c1);
    }
    float v2_0 = 0.f, v2_1 = 0.f, c2 = 0.f;
    #pragma unroll
    for (int k = 0; k < 9; k++) {
        float d0 = win[0][k] - mean0;
        float d1 = win[1][k] - mean1;
        v2_0 = fmaf(d0 * d0, qv[k], v2_0);
        v2_1 = fmaf(d1 * d1, qv[k], v2_1);
        c2   = fmaf(d0 * d1, qv[k], c2);
    }

    out[((b * CTOT + 64) * Hdim + h) * Wdim + w] = mean0;
    out[((b * CTOT + 65) * Hdim + h) * Wdim + w] = mean1;
    out[((b * CTOT + 66) * Hdim + h) * Wdim + w] = v1_0 + v2_0;
    out[((b * CTOT + 67) * Hdim + h) * Wdim + w] = v1_1 + v2_1;
    out[((b * CTOT + 68) * Hdim + h) * Wdim + w] = c1 + c2;
}

// ---------------------------------------------------------------------------
extern "C" void kernel_launch(void* const* d_in, const int* in_sizes, int n_in,
                              void* d_out, int out_size)
{
    const float* x   = (const float*)d_in[0];
    const float* cw  = (const float*)d_in[1];
    const float* cb  = (const float*)d_in[2];
    const float* c2w = (const float*)d_in[3];
    const float* c2b = (const float*)d_in[4];
    const float* sk  = (const float*)d_in[5];
    float* out = (float*)d_out;

    static bool attr_set = false;
    if (!attr_set) {
        cudaFuncSetAttribute(conv_mma_kernel,
                             cudaFuncAttributeMaxDynamicSharedMemorySize, DYN_SMEM);
        cudaFuncSetAttribute(attend_mma_kernel,
                             cudaFuncAttributeMaxDynamicSharedMemorySize, AT3_DYN_SMEM);
        attr_set = true;
    }

    prep_kernel<<<(PREP_TOT + 255) / 256, 256>>>(cw, sk);
    conv_mma_kernel<<<256, 256, DYN_SMEM>>>(x, cb);
    bn_finalize<<<64, 256>>>();
    attend_mma_kernel<<<NPIX / 64, 256, AT3_DYN_SMEM>>>(x, c2w, c2b, out);
    agg_kernel<<<NPIX / 256, 256>>>(x, out);
}

// round 14
// speedup vs baseline: 1.1758x; 1.0765x over previous
#include <cuda_runtime.h>
#include <cstdint>

#define BATCH 8
#define CIN   64
#define COUT  64
#define Hdim  64
#define Wdim  64
#define CTOT  69
#define HW    (Hdim*Wdim)
#define NPIX  (BATCH*HW)

// Scratch (static device globals — no allocation)
__device__ float g_conv[BATCH*COUT*HW];   // raw conv output (pre-BN)
__device__ float g_sq[NPIX];              // 1x1-conv "shape query"
__device__ float g_mu[COUT];
__device__ float g_rs[COUT];
__device__ float g_psum[COUT*256];        // per-(co, conv-block) partials
__device__ float g_psumsq[COUT*256];
__device__ __align__(16) float g_wt[9*4096];   // conv weights, B-fragment order
__device__ __align__(16) float g_bhi[48*72];   // codebook 2k hi, [t][co]
__device__ __align__(16) float g_blo[48*72];   // codebook 2k lo
__device__ float g_k2v[64];                    // |k|^2 per code

__device__ __forceinline__ int clampi(int v, int lo, int hi) {
    return v < lo ? lo : (v > hi ? hi : v);
}
__device__ __forceinline__ float f2tf32f(float f) {
    uint32_t r; asm("cvt.rna.tf32.f32 %0, %1;" : "=r"(r) : "f"(f));
    return __uint_as_float(r);
}

// m16n8k8 tf32 mma: D += A*B (D==C, fp32 accum). a: 4 regs, b: 2 regs.
__device__ __forceinline__ void mma8(float* d, const uint32_t* a, uint32_t b0, uint32_t b1) {
    asm volatile(
        "mma.sync.aligned.m16n8k8.row.col.f32.tf32.tf32.f32 "
        "{%0,%1,%2,%3}, {%4,%5,%6,%7}, {%8,%9}, {%0,%1,%2,%3};\n"
        : "+f"(d[0]), "+f"(d[1]), "+f"(d[2]), "+f"(d[3])
        : "r"(a[0]), "r"(a[1]), "r"(a[2]), "r"(a[3]), "r"(b0), "r"(b1));
}

// ---------------------------------------------------------------------------
// Kernel 0: prep — conv weight fragment transform + codebook hi/lo + |k|^2
// ---------------------------------------------------------------------------
#define PREP_WT   (9*4096)
#define PREP_B    (48*72)
#define PREP_TOT  (PREP_WT + PREP_B + 64)

__global__ __launch_bounds__(256) void prep_kernel(
    const float* __restrict__ cw, const float* __restrict__ sk)
{
    int idx = blockIdx.x * 256 + threadIdx.x;
    if (idx < PREP_WT) {
        int r    = idx & 1;
        int lane = (idx >> 1) & 31;
        int nt   = (idx >> 6) & 7;
        int kk   = (idx >> 9) & 7;
        int kidx = idx >> 12;
        int gid = lane >> 2, tig = lane & 3;
        int co = nt * 8 + gid;
        int ci = kk * 8 + tig + 4 * r;
        g_wt[idx] = f2tf32f(cw[(co * CIN + ci) * 9 + kidx]);
    } else if (idx < PREP_WT + PREP_B) {
        int i  = idx - PREP_WT;
        int t  = i / 72;
        int co = i - t * 72;
        float val = (co < 64 && t < 45) ? 2.f * sk[co * 45 + t] : 0.f;
        float hi  = f2tf32f(val);
        g_bhi[i] = hi;
        g_blo[i] = f2tf32f(val - hi);
    } else if (idx < PREP_TOT) {
        int co = idx - PREP_WT - PREP_B;
        float a = 0.f;
        for (int t = 0; t < 45; t++) {
            float kv = sk[co * 45 + t];
            a = fmaf(kv, kv, a);
        }
        g_k2v[co] = a;
    }
}

// ---------------------------------------------------------------------------
// Kernel 1: 3x3 conv via mma.sync tf32 implicit GEMM + fused BN partials.
// bbuf now DOUBLE-BUFFERED: one __syncthreads per (ky,kx) chunk.
// ---------------------------------------------------------------------------
#define SLAB_STRIDE 264
#define SLAB_FLOATS (64*SLAB_STRIDE)
#define BBUF_FLOATS 4096
#define DYN_SMEM ((SLAB_FLOATS + 2*BBUF_FLOATS) * 4)   // 100352 B

__global__ __launch_bounds__(256, 2) void conv_mma_kernel(
    const float* __restrict__ x, const float* __restrict__ cb)
{
    extern __shared__ float smem[];
    float* slab = smem;
    float* bbuf0 = smem + SLAB_FLOATS;

    const int tid  = threadIdx.x;
    const int lane = tid & 31;
    const int w    = tid >> 5;
    const int gid  = lane >> 2;
    const int tig  = lane & 3;
    const int wm   = (w & 3) * 32;
    const int wn   = (w >> 2) * 32;
    const int blk  = blockIdx.x;
    const int b    = blk >> 5;
    const int h0   = (blk & 31) * 2;

    const float* xb = x + (size_t)b * CTOT * HW;
    #pragma unroll
    for (int i = 0; i < 64; i++) {
        int idx = i * 256 + tid;
        int ci  = idx >> 8;
        int rc  = idx & 255;
        int rr  = rc >> 6;
        int col = rc & 63;
        int row = clampi(h0 - 1 + rr, 0, Hdim - 1);
        slab[ci * SLAB_STRIDE + rc] = f2tf32f(__ldg(xb + (ci * Hdim + row) * Wdim + col));
    }

    const float4* wt4 = (const float4*)g_wt;
    float4 pf[4];
    #pragma unroll
    for (int j = 0; j < 4; j++) pf[j] = __ldg(wt4 + j * 256 + tid);

    float acc[2][4][4];
    #pragma unroll
    for (int tm = 0; tm < 2; tm++)
        #pragma unroll
        for (int nt = 0; nt < 4; nt++)
            #pragma unroll
            for (int c = 0; c < 4; c++) acc[tm][nt][c] = 0.f;

    __syncthreads();   // slab ready

    int dy[2], col_lo[2], col_hi[2];
    #pragma unroll
    for (int tm = 0; tm < 2; tm++) {
        int pix = wm + tm * 16 + gid;
        dy[tm] = pix >> 6;
        col_lo[tm] = pix & 63;
        col_hi[tm] = col_lo[tm] + 8;
    }

    for (int kidx = 0; kidx < 9; kidx++) {
        const int ky = kidx / 3, kx = kidx % 3;
        float* bbuf = bbuf0 + (kidx & 1) * BBUF_FLOATS;
        float4* bb4 = (float4*)bbuf;
        #pragma unroll
        for (int j = 0; j < 4; j++) bb4[j * 256 + tid] = pf[j];
        __syncthreads();   // publish this chunk (also closes kidx-1 compute)
        if (kidx < 8) {
            #pragma unroll
            for (int j = 0; j < 4; j++)
                pf[j] = __ldg(wt4 + (kidx + 1) * 1024 + j * 256 + tid);
        }

        int off_lo[2], off_hi[2];
        #pragma unroll
        for (int tm = 0; tm < 2; tm++) {
            int rowoff = (dy[tm] + ky) * 64;
            off_lo[tm] = rowoff + clampi(col_lo[tm] + kx - 1, 0, 63);
            off_hi[tm] = rowoff + clampi(col_hi[tm] + kx - 1, 0, 63);
        }

        #pragma unroll
        for (int kk = 0; kk < 8; kk++) {
            const int cib  = (kk * 8 + tig) * SLAB_STRIDE;
            const int cib4 = cib + 4 * SLAB_STRIDE;
            uint32_t a[2][4];
            #pragma unroll
            for (int tm = 0; tm < 2; tm++) {
                a[tm][0] = __float_as_uint(slab[cib  + off_lo[tm]]);
                a[tm][1] = __float_as_uint(slab[cib  + off_hi[tm]]);
                a[tm][2] = __float_as_uint(slab[cib4 + off_lo[tm]]);
                a[tm][3] = __float_as_uint(slab[cib4 + off_hi[tm]]);
            }
            #pragma unroll
            for (int nt = 0; nt < 4; nt++) {
                int ntg = (wn >> 3) + nt;
                float2 bf = *(const float2*)&bbuf[((kk * 8 + ntg) * 32 + lane) * 2];
                uint32_t b0 = __float_as_uint(bf.x);
                uint32_t b1 = __float_as_uint(bf.y);
                mma8(acc[0][nt], a[0], b0, b1);
                mma8(acc[1][nt], a[1], b0, b1);
            }
        }
    }

    // ---- epilogue: +bias, write g_conv, accumulate BN partials ----
    float ps[4][2], ps2[4][2];
    #pragma unroll
    for (int nt = 0; nt < 4; nt++) {
        ps[nt][0] = ps[nt][1] = 0.f;
        ps2[nt][0] = ps2[nt][1] = 0.f;
    }
    #pragma unroll
    for (int tm = 0; tm < 2; tm++) {
        float* grow = g_conv + ((size_t)b * COUT * Hdim + (h0 + dy[tm])) * Wdim;
        #pragma unroll
        for (int nt = 0; nt < 4; nt++) {
            int co0 = wn + nt * 8 + 2 * tig;
            float b0 = __ldg(cb + co0), b1 = __ldg(cb + co0 + 1);
            float v0 = acc[tm][nt][0] + b0;
            float v1 = acc[tm][nt][1] + b1;
            float v2 = acc[tm][nt][2] + b0;
            float v3 = acc[tm][nt][3] + b1;
            grow[(size_t)co0       * HW + col_lo[tm]] = v0;
            grow[(size_t)(co0 + 1) * HW + col_lo[tm]] = v1;
            grow[(size_t)co0       * HW + col_hi[tm]] = v2;
            grow[(size_t)(co0 + 1) * HW + col_hi[tm]] = v3;
            ps[nt][0]  += v0 + v2;
            ps2[nt][0] += v0 * v0 + v2 * v2;
            ps[nt][1]  += v1 + v3;
            ps2[nt][1] += v1 * v1 + v3 * v3;
        }
    }

    __syncthreads();              // slab/bbuf dead -> overlay reduction area
    float* sred = smem;           // [8 warps][64] : [0:32)=s, [32:64)=s2
    #pragma unroll
    for (int nt = 0; nt < 4; nt++) {
        #pragma unroll
        for (int cc = 0; cc < 2; cc++) {
            float s = ps[nt][cc], s2 = ps2[nt][cc];
            s  += __shfl_xor_sync(0xffffffffu, s,  4);
            s  += __shfl_xor_sync(0xffffffffu, s,  8);
            s  += __shfl_xor_sync(0xffffffffu, s, 16);
            s2 += __shfl_xor_sync(0xffffffffu, s2,  4);
            s2 += __shfl_xor_sync(0xffffffffu, s2,  8);
            s2 += __shfl_xor_sync(0xffffffffu, s2, 16);
            if (gid == 0) {
                int ci = nt * 8 + 2 * tig + cc;
                sred[w * 64 + ci]      = s;
                sred[w * 64 + 32 + ci] = s2;
            }
        }
    }
    __syncthreads();
    if (tid < 64) {
        int co = tid;
        int wb = (co >> 5) * 4;
        int cl = co & 31;
        float s = 0.f, s2 = 0.f;
        #pragma unroll
        for (int i = 0; i < 4; i++) {
            s  += sred[(wb + i) * 64 + cl];
            s2 += sred[(wb + i) * 64 + 32 + cl];
        }
        g_psum[co * 256 + blk]   = s;
        g_psumsq[co * 256 + blk] = s2;
    }
}

// ---------------------------------------------------------------------------
// Kernel 2: BN finalize — reduce 256 partials per channel (deterministic)
// ---------------------------------------------------------------------------
__global__ __launch_bounds__(256) void bn_finalize()
{
    __shared__ float ss[256], ss2[256];
    const int co = blockIdx.x;
    const int t  = threadIdx.x;
    ss[t]  = g_psum[co * 256 + t];
    ss2[t] = g_psumsq[co * 256 + t];
    __syncthreads();
    for (int o = 128; o > 0; o >>= 1) {
        if (t < o) { ss[t] += ss[t + o]; ss2[t] += ss2[t + o]; }
        __syncthreads();
    }
    if (t == 0) {
        float n   = (float)(BATCH * HW);
        float mu  = ss[0] / n;
        float var = ss2[0] / n - mu * mu;
        g_mu[co] = mu;
        g_rs[co] = rsqrtf(var + 1e-5f);
    }
}

// ---------------------------------------------------------------------------
// Kernel 3: attend via 3xTF32 mma.sync. 64 pixels/block, 512 blocks.
// g_conv values for the final pass are PREFETCHED right after the MMA loop
// so their memory latency overlaps the softmax phases.
// ---------------------------------------------------------------------------
#define A3_STRIDE 52
#define B3_STRIDE 72
#define SW3_STRIDE 66
#define AT3_AHI  0
#define AT3_ALO  (64*A3_STRIDE)
#define AT3_BHI  (2*64*A3_STRIDE)
#define AT3_BLO  (AT3_BHI + 48*B3_STRIDE)
#define AT3_REGION (AT3_BLO + 48*B3_STRIDE)
#define AT3_REDM AT3_REGION
#define AT3_REDS (AT3_REDM + 128)
#define AT3_SQP  (AT3_REDS + 128)
#define AT3_K2   (AT3_SQP + 256)
#define AT3_MU   (AT3_K2 + 64)
#define AT3_RS   (AT3_MU + 64)
#define AT3_W2   (AT3_RS + 64)
#define AT3_FLOATS (AT3_W2 + 64)
#define AT3_DYN_SMEM (AT3_FLOATS * 4)       // ~57 KB

__global__ __launch_bounds__(256, 3) void attend_mma_kernel(
    const float* __restrict__ x,
    const float* __restrict__ c2w, const float* __restrict__ c2b,
    float* __restrict__ out)
{
    extern __shared__ float sm[];
    float* sAhi = sm + AT3_AHI;
    float* sAlo = sm + AT3_ALO;
    float* sBhi = sm + AT3_BHI;
    float* sBlo = sm + AT3_BLO;
    float* sW   = sm;                      // overlay after MMA
    float* sRm  = sm + AT3_REDM;
    float* sRs_ = sm + AT3_REDS;
    float* sSQP = sm + AT3_SQP;
    float* sK2  = sm + AT3_K2;
    float* sMu  = sm + AT3_MU;
    float* sRs  = sm + AT3_RS;
    float* sW2  = sm + AT3_W2;

    const int tid  = threadIdx.x;
    const int lane = tid & 31;
    const int warp = tid >> 5;
    const int gid  = lane >> 2;
    const int tig  = lane & 3;

    // ---- copy precomputed B hi/lo (coalesced float4) + constants ----
    {
        const float4* bh4 = (const float4*)g_bhi;
        const float4* bl4 = (const float4*)g_blo;
        float4* dh4 = (float4*)sBhi;
        float4* dl4 = (float4*)sBlo;
        #pragma unroll
        for (int i = tid; i < (48 * B3_STRIDE) / 4; i += 256) {
            dh4[i] = __ldg(bh4 + i);
            dl4[i] = __ldg(bl4 + i);
        }
    }
    if (tid < 64) {
        sK2[tid] = g_k2v[tid];
        sMu[tid] = g_mu[tid];
        sRs[tid] = g_rs[tid];
        sW2[tid] = c2w[tid];
    }

    // ---- window build: quarter q handles channel subset for its pixel ----
    const int pix = tid & 63;
    const int q   = tid >> 6;
    const int p   = blockIdx.x * 64 + pix;
    const int b   = p >> 12;
    const int hw  = p & 4095;
    const int h   = hw >> 6;
    const int w   = hw & 63;

    if (q < 2) {
        int c = q;
        float v[9];
        #pragma unroll
        for (int i = 0; i < 3; i++)
            #pragma unroll
            for (int j = 0; j < 3; j++) {
                int gy = clampi(h + i - 1, 0, Hdim - 1);
                int gx = clampi(w + j - 1, 0, Wdim - 1);
                v[i * 3 + j] = x[((b * CTOT + 64 + c) * Hdim + gy) * Wdim + gx];
            }
        float ctr = v[4];
        #pragma unroll
        for (int k = 0; k < 9; k++) {
            float val = v[k] - ctr;
            float hi  = f2tf32f(val);
            sAhi[pix * A3_STRIDE + c * 9 + k] = hi;
            sAlo[pix * A3_STRIDE + c * 9 + k] = f2tf32f(val - hi);
        }
        if (q == 0) {
            #pragma unroll
            for (int t = 45; t < 48; t++) {
                sAhi[pix * A3_STRIDE + t] = 0.f;
                sAlo[pix * A3_STRIDE + t] = 0.f;
            }
        }
    } else if (q == 2) {
        #pragma unroll
        for (int c = 2; c < 4; c++)
            #pragma unroll
            for (int i = 0; i < 3; i++)
                #pragma unroll
                for (int j = 0; j < 3; j++) {
                    int gy = clampi(h + i - 1, 0, Hdim - 1);
                    int gx = clampi(w + j - 1, 0, Wdim - 1);
                    float val = x[((b * CTOT + 64 + c) * Hdim + gy) * Wdim + gx];
                    float hi  = f2tf32f(val);
                    sAhi[pix * A3_STRIDE + c * 9 + i * 3 + j] = hi;
                    sAlo[pix * A3_STRIDE + c * 9 + i * 3 + j] = f2tf32f(val - hi);
                }
    } else {
        #pragma unroll
        for (int i = 0; i < 3; i++)
            #pragma unroll
            for (int j = 0; j < 3; j++) {
                int gy = clampi(h + i - 1, 0, Hdim - 1);
                int gx = clampi(w + j - 1, 0, Wdim - 1);
                float val = x[((b * CTOT + 68) * Hdim + gy) * Wdim + gx];
                float hi  = f2tf32f(val);
                sAhi[pix * A3_STRIDE + 36 + i * 3 + j] = hi;
                sAlo[pix * A3_STRIDE + 36 + i * 3 + j] = f2tf32f(val - hi);
            }
    }
    __syncthreads();

    // ---- MMA: warp pair (warp>>1) -> 16-row strip; coHalf = warp&1 ----
    const int rstrip = (warp >> 1) * 16;
    const int coHalf = warp & 1;
    const int nt0    = coHalf * 4;

    float acc[4][4];
    #pragma unroll
    for (int nt = 0; nt < 4; nt++)
        #pragma unroll
        for (int c = 0; c < 4; c++) acc[nt][c] = 0.f;

    #pragma unroll
    for (int ks = 0; ks < 6; ks++) {
        uint32_t ah[4], al[4];
        {
            int r0 = rstrip + gid;
            int o  = ks * 8 + tig;
            ah[0] = __float_as_uint(sAhi[r0 * A3_STRIDE + o]);
            ah[1] = __float_as_uint(sAhi[(r0 + 8) * A3_STRIDE + o]);
            ah[2] = __float_as_uint(sAhi[r0 * A3_STRIDE + o + 4]);
            ah[3] = __float_as_uint(sAhi[(r0 + 8) * A3_STRIDE + o + 4]);
            al[0] = __float_as_uint(sAlo[r0 * A3_STRIDE + o]);
            al[1] = __float_as_uint(sAlo[(r0 + 8) * A3_STRIDE + o]);
            al[2] = __float_as_uint(sAlo[r0 * A3_STRIDE + o + 4]);
            al[3] = __float_as_uint(sAlo[(r0 + 8) * A3_STRIDE + o + 4]);
        }
        #pragma unroll
        for (int ntl = 0; ntl < 4; ntl++) {
            int nt = nt0 + ntl;
            int r1 = (ks * 8 + tig) * B3_STRIDE + nt * 8 + gid;
            int r2 = (ks * 8 + tig + 4) * B3_STRIDE + nt * 8 + gid;
            uint32_t uh0 = __float_as_uint(sBhi[r1]);
            uint32_t uh1 = __float_as_uint(sBhi[r2]);
            uint32_t ul0 = __float_as_uint(sBlo[r1]);
            uint32_t ul1 = __float_as_uint(sBlo[r2]);
            mma8(acc[ntl], ah, uh0, uh1);
            mma8(acc[ntl], al, uh0, uh1);
            mma8(acc[ntl], ah, ul0, ul1);
        }
    }

    // ---- PREFETCH g_conv for the final pass (overlaps softmax latency) ----
    const float* gc = g_conv + (size_t)b * COUT * HW + hw;
    const int cb0 = q * 16;
    float cvv[16];
    #pragma unroll
    for (int j = 0; j < 16; j++)
        cvv[j] = __ldg(gc + (size_t)(cb0 + j) * HW);

    __syncthreads();   // all A/B reads done (before sW overlay writes)

    // ---- softmax phase 1: logits & per-warp partial max ----
    #pragma unroll
    for (int h8 = 0; h8 < 2; h8++) {
        float m = -3.4e38f;
        #pragma unroll
        for (int ntl = 0; ntl < 4; ntl++) {
            #pragma unroll
            for (int cc = 0; cc < 2; cc++) {
                int co = coHalf * 32 + ntl * 8 + 2 * tig + cc;
                float l = acc[ntl][2 * h8 + cc] - sK2[co];
                acc[ntl][2 * h8 + cc] = l;
                m = fmaxf(m, l);
            }
        }
        m = fmaxf(m, __shfl_xor_sync(0xffffffffu, m, 1));
        m = fmaxf(m, __shfl_xor_sync(0xffffffffu, m, 2));
        if (tig == 0) sRm[coHalf * 64 + rstrip + gid + 8 * h8] = m;
    }
    __syncthreads();

    // ---- phase 2: combined max, exp, partial sums ----
    #pragma unroll
    for (int h8 = 0; h8 < 2; h8++) {
        int row = rstrip + gid + 8 * h8;
        float m = fmaxf(sRm[row], sRm[64 + row]);
        float s = 0.f;
        #pragma unroll
        for (int ntl = 0; ntl < 4; ntl++) {
            #pragma unroll
            for (int cc = 0; cc < 2; cc++) {
                float e = __expf(acc[ntl][2 * h8 + cc] - m);
                acc[ntl][2 * h8 + cc] = e;
                s += e;
            }
        }
        s += __shfl_xor_sync(0xffffffffu, s, 1);
        s += __shfl_xor_sync(0xffffffffu, s, 2);
        if (tig == 0) sRs_[coHalf * 64 + row] = s;
    }
    __syncthreads();

    // ---- phase 3: normalize & transpose into sW[co][row] ----
    #pragma unroll
    for (int h8 = 0; h8 < 2; h8++) {
        int row = rstrip + gid + 8 * h8;
        float inv = 1.f / (sRs_[row] + sRs_[64 + row]);
        #pragma unroll
        for (int ntl = 0; ntl < 4; ntl++) {
            #pragma unroll
            for (int cc = 0; cc < 2; cc++) {
                int co = coHalf * 32 + ntl * 8 + 2 * tig + cc;
                sW[co * SW3_STRIDE + row] = acc[ntl][2 * h8 + cc] * inv;
            }
        }
    }
    __syncthreads();

    // ---- final coalesced pass: quarter q owns 16 codes ----
    float* op = out + (size_t)b * CTOT * HW + hw;
    float sq = 0.f;
    #pragma unroll
    for (int j = 0; j < 16; j++) {
        int co = cb0 + j;
        float ww  = sW[co * SW3_STRIDE + pix];
        float cv  = (cvv[j] - sMu[co]) * sRs[co];
        float att = fmaxf(cv * ww, 0.f);
        op[(size_t)co * HW] = att;
        sq = fmaf(sW2[co], att, sq);
    }
    sSQP[q * 64 + pix] = sq;
    __syncthreads();
    if (q == 0)
        g_sq[p] = sSQP[pix] + sSQP[64 + pix] + sSQP[128 + pix] + sSQP[192 + pix]
                + __ldg(c2b);
}

// ---------------------------------------------------------------------------
// Kernel 4: window softmax of shape query (zero-padded) + weighted stats.
// Re-gridded: 256 blocks x 128 threads (was 128x256) for full-chip spread.
// ---------------------------------------------------------------------------
__global__ __launch_bounds__(128) void agg_kernel(
    const float* __restrict__ x, float* __restrict__ out)
{
    const int p = blockIdx.x * 128 + threadIdx.x;
    const int b  = p >> 12;
    const int hw = p & 4095;
    const int h  = hw >> 6;
    const int w  = hw & 63;

    float qv[9];
    float qmax = -3.4e38f;
    #pragma unroll
    for (int i = 0; i < 3; i++)
        #pragma unroll
        for (int j = 0; j < 3; j++) {
            int yy = h + i - 1, xx = w + j - 1;
            float v = 0.f;
            if (yy >= 0 && yy < Hdim && xx >= 0 && xx < Wdim)
                v = g_sq[(b << 12) + (yy << 6) + xx];
            qv[i * 3 + j] = v;
            qmax = fmaxf(qmax, v);
        }
    float qs = 0.f;
    #pragma unroll
    for (int k = 0; k < 9; k++) { qv[k] = __expf(qv[k] - qmax); qs += qv[k]; }
    float qinv = 1.f / qs;
    #pragma unroll
    for (int k = 0; k < 9; k++) qv[k] *= qinv;

    float win[5][9];
    #pragma unroll
    for (int c = 0; c < 5; c++) {
        #pragma unroll
        for (int i = 0; i < 3; i++)
            #pragma unroll
            for (int j = 0; j < 3; j++) {
                int gy = clampi(h + i - 1, 0, Hdim - 1);
                int gx = clampi(w + j - 1, 0, Wdim - 1);
                win[c][i * 3 + j] = x[((b * CTOT + 64 + c) * Hdim + gy) * Wdim + gx];
            }
    }

    float mean0 = 0.f, mean1 = 0.f, v1_0 = 0.f, v1_1 = 0.f, c1 = 0.f;
    #pragma unroll
    for (int k = 0; k < 9; k++) {
        mean0 = fmaf(win[0][k], qv[k], mean0);
        mean1 = fmaf(win[1][k], qv[k], mean1);
        v1_0  = fmaf(win[2][k], qv[k], v1_0);
        v1_1  = fmaf(win[3][k], qv[k], v1_1);
        c1    = fmaf(win[4][k], qv[k], c1);
    }
    float v2_0 = 0.f, v2_1 = 0.f, c2 = 0.f;
    #pragma unroll
    for (int k = 0; k < 9; k++) {
        float d0 = win[0][k] - mean0;
        float d1 = win[1][k] - mean1;
        v2_0 = fmaf(d0 * d0, qv[k], v2_0);
        v2_1 = fmaf(d1 * d1, qv[k], v2_1);
        c2   = fmaf(d0 * d1, qv[k], c2);
    }

    out[((b * CTOT + 64) * Hdim + h) * Wdim + w] = mean0;
    out[((b * CTOT + 65) * Hdim + h) * Wdim + w] = mean1;
    out[((b * CTOT + 66) * Hdim + h) * Wdim + w] = v1_0 + v2_0;
    out[((b * CTOT + 67) * Hdim + h) * Wdim + w] = v1_1 + v2_1;
    out[((b * CTOT + 68) * Hdim + h) * Wdim + w] = c1 + c2;
}

// ---------------------------------------------------------------------------
extern "C" void kernel_launch(void* const* d_in, const int* in_sizes, int n_in,
                              void* d_out, int out_size)
{
    const float* x   = (const float*)d_in[0];
    const float* cw  = (const float*)d_in[1];
    const float* cb  = (const float*)d_in[2];
    const float* c2w = (const float*)d_in[3];
    const float* c2b = (const float*)d_in[4];
    const float* sk  = (const float*)d_in[5];
    float* out = (float*)d_out;

    static bool attr_set = false;
    if (!attr_set) {
        cudaFuncSetAttribute(conv_mma_kernel,
                             cudaFuncAttributeMaxDynamicSharedMemorySize, DYN_SMEM);
        cudaFuncSetAttribute(attend_mma_kernel,
                             cudaFuncAttributeMaxDynamicSharedMemorySize, AT3_DYN_SMEM);
        attr_set = true;
    }

    prep_kernel<<<(PREP_TOT + 255) / 256, 256>>>(cw, sk);
    conv_mma_kernel<<<256, 256, DYN_SMEM>>>(x, cb);
    bn_finalize<<<64, 256>>>();
    attend_mma_kernel<<<NPIX / 64, 256, AT3_DYN_SMEM>>>(x, c2w, c2b, out);
    agg_kernel<<<NPIX / 128, 128>>>(x, out);
}